// round 16
// baseline (speedup 1.0000x reference)
#include <cuda_runtime.h>
#include <math.h>
#include <stdint.h>

#define BB 8
#define NN 2048
#define MM 2048
#define STRIDE 512            /* max sparse entries per row/col in gmem ELL */
#define PAIRS (STRIDE / 2)
#define NITER 100
#define CL 8                  /* CTAs per cluster (= per batch) */
#define SLICE 256             /* rows/cols owned per CTA        */
#define RSTAGE 22             /* pair slots per thread resident in SMEM     */
#define TXB 8192u             /* per-phase incoming: 8 ranks x 256 x 4B (incl. self) */

#define KFLOOR 1.9287498479639178e-22f   /* fp32(exp(-50)) */
#define MUV    4.8828125e-4f             /* 1/2048 */
#define EPSDIV 1e-8f

static __device__ __forceinline__ float uaf(unsigned x) { return __uint_as_float(x); }

// ---- static device scratch (no runtime allocations allowed) ----
__device__ uint4 g_rell4[(size_t)BB * PAIRS * NN];   // (j, Ktilde)    row-major ELL
__device__ uint4 g_cell4[(size_t)BB * PAIRS * MM];   // (i, Ktilde)    col-major ELL
__device__ uint4 g_eell4[(size_t)BB * PAIRS * NN];   // (j, Ktilde*d)  row-major ELL (emd)
__device__ int   g_rcnt[BB * NN];
__device__ int   g_ccnt[BB * MM];
__device__ float g_u[BB * NN];
__device__ float g_v[BB * MM];
__device__ float g_accum;

// ---- dynamic SMEM (~197 KB) ----
struct SKm {
    float u[NN];
    float v[MM];
    uint4 bufR[RSTAGE * 256];   // resident row entries, layout [k][tid], zero-padded
    uint4 bufC[RSTAGE * 256];   // resident col entries, zero-padded
    unsigned long long mbu, mbv;
};

// ---- cluster / DSMEM / mbarrier helpers ----
static __device__ __forceinline__ uint32_t smem_u32(const void* p) {
    return (uint32_t)__cvta_generic_to_shared(p);
}
static __device__ __forceinline__ uint32_t mapa_sh(uint32_t addr, uint32_t rank) {
    uint32_t o;
    asm("mapa.shared::cluster.u32 %0, %1, %2;" : "=r"(o) : "r"(addr), "r"(rank));
    return o;
}
static __device__ __forceinline__ void st_async128(uint32_t daddr, unsigned a, unsigned bq,
                                                   unsigned c, unsigned d, uint32_t dmbar) {
    asm volatile("st.async.shared::cluster.mbarrier::complete_tx::bytes.v4.b32 "
                 "[%0], {%1, %2, %3, %4}, [%5];"
                 :: "r"(daddr), "r"(a), "r"(bq), "r"(c), "r"(d), "r"(dmbar) : "memory");
}
static __device__ __forceinline__ void mb_init(uint32_t mb, uint32_t cnt) {
    asm volatile("mbarrier.init.shared.b64 [%0], %1;" :: "r"(mb), "r"(cnt) : "memory");
}
static __device__ __forceinline__ void mb_expect(uint32_t mb, uint32_t tx) {
    asm volatile("mbarrier.arrive.expect_tx.shared.b64 _, [%0], %1;" :: "r"(mb), "r"(tx) : "memory");
}
static __device__ __forceinline__ void mb_wait(uint32_t mb, uint32_t parity) {
    uint32_t done;
    asm volatile("{\n\t.reg .pred p;\n\t"
                 "mbarrier.try_wait.parity.acquire.cluster.shared::cta.b64 p, [%1], %2;\n\t"
                 "selp.b32 %0, 1, 0, p;\n\t}"
                 : "=r"(done) : "r"(mb), "r"(parity) : "memory");
    while (!done) {
        asm volatile("{\n\t.reg .pred p;\n\t"
                     "mbarrier.try_wait.parity.acquire.cluster.shared::cta.b64 p, [%1], %2, 0x989680;\n\t"
                     "selp.b32 %0, 1, 0, p;\n\t}"
                     : "=r"(done) : "r"(mb), "r"(parity) : "memory");
    }
}
#define CLUSTER_SYNC() do {                                                 \
    asm volatile("barrier.cluster.arrive.aligned;" ::: "memory");           \
    asm volatile("barrier.cluster.wait.aligned;"   ::: "memory");           \
} while (0)

// ---------------------------------------------------------------------------
__global__ void init_kernel() {
    int t = blockIdx.x * blockDim.x + threadIdx.x;
    if (t < BB * MM) g_ccnt[t] = 0;
    if (t == 0) g_accum = 0.0f;
}

// ---------------------------------------------------------------------------
// Build sparse correction lists where d^2 < 0.25 (100*d < 50); elsewhere
// K == exp(-50) exactly (same bits as the reference clamp).
__global__ void build_kernel(const float* __restrict__ src, const float* __restrict__ tgt) {
    const int b = blockIdx.y;
    __shared__ float tx[MM], ty[MM], tz[MM];
    const float* T = tgt + (size_t)b * MM * 3;
    for (int j = threadIdx.x; j < MM; j += blockDim.x) {
        tx[j] = T[3 * j + 0];
        ty[j] = T[3 * j + 1];
        tz[j] = T[3 * j + 2];
    }
    __syncthreads();

    const int warp = threadIdx.x >> 5, lane = threadIdx.x & 31;
    const int nwarps = blockDim.x >> 5;
    const int rows_per_cta = NN / gridDim.x;
    const int row0 = blockIdx.x * rows_per_cta;
    const float* S = src + (size_t)b * NN * 3;
    uint2* rell2 = (uint2*)(g_rell4 + (size_t)b * PAIRS * NN);
    uint2* eell2 = (uint2*)(g_eell4 + (size_t)b * PAIRS * NN);
    uint2* cell2 = (uint2*)(g_cell4 + (size_t)b * PAIRS * MM);

    for (int i = row0 + warp; i < row0 + rows_per_cta; i += nwarps) {
        const float sx = S[3 * i + 0], sy = S[3 * i + 1], sz = S[3 * i + 2];
        int rbase = 0;
        for (int j0 = 0; j0 < MM; j0 += 32) {
            const int j = j0 + lane;
            float dx = sx - tx[j];
            float dy = sy - ty[j];
            float dz = sz - tz[j];
            float s = fmaf(dx, dx, fmaf(dy, dy, dz * dz));
            bool pred = (s < 0.25f);
            unsigned mask = __ballot_sync(0xffffffffu, pred);
            if (pred) {
                float d = sqrtf(s);
                float kt = expf(-100.0f * d) - KFLOOR;
                int k = rbase + __popc(mask & ((1u << lane) - 1u));
                if (k < STRIDE) {
                    size_t i2 = ((size_t)(k >> 1) * NN + i) * 2 + (k & 1);
                    rell2[i2] = make_uint2((unsigned)j, __float_as_uint(kt));
                    eell2[i2] = make_uint2((unsigned)j, __float_as_uint(kt * d));
                }
                int kc = atomicAdd(&g_ccnt[b * MM + j], 1);
                if (kc < STRIDE)
                    cell2[((size_t)(kc >> 1) * MM + j) * 2 + (kc & 1)] =
                        make_uint2((unsigned)i, __float_as_uint(kt));
            }
            rbase += __popc(mask);
        }
        int cap = (rbase < STRIDE) ? rbase : STRIDE;
        if (lane == 0) {
            g_rcnt[b * NN + i] = cap;
            if (cap & 1) {   // zero-pad ELL odd tail (cap==STRIDE is even)
                size_t i2 = ((size_t)(cap >> 1) * NN + i) * 2 + 1;
                rell2[i2] = make_uint2(0u, 0u);
                eell2[i2] = make_uint2(0u, 0u);
            }
        }
    }
}

// Clamp column counts + zero-pad odd tails of the column lists.
__global__ void colfix_kernel() {
    int t = blockIdx.x * blockDim.x + threadIdx.x;
    if (t >= BB * MM) return;
    int c = g_ccnt[t];
    if (c > STRIDE) c = STRIDE;
    g_ccnt[t] = c;
    if (c & 1) {
        int b = t / MM, j = t - b * MM;
        uint2* cell2 = (uint2*)(g_cell4 + (size_t)b * PAIRS * MM);
        cell2[((size_t)(c >> 1) * MM + j) * 2 + 1] = make_uint2(0u, 0u);
    }
}

// ---------------------------------------------------------------------------
// 256 threads/CTA, one thread per owned row+col. ELL lists resident in SMEM,
// ZERO-PADDED to a fixed RSTAGE slots -> compile-time-trip gather loop whose
// 22 LDS.128 are front-batchable. Broadcast: every 4th thread packs 4 values
// and sends ONE 16B st.async.v4 per rank (512 msgs/CTA-phase, was 1024).
__global__ void __launch_bounds__(256, 1) __cluster_dims__(CL, 1, 1)
sinkhorn_kernel() {
    extern __shared__ char raw[];
    SKm* S = (SKm*)raw;
    uint32_t crank;
    asm("mov.u32 %0, %%cluster_ctarank;" : "=r"(crank));
    const int b    = blockIdx.x >> 3;
    const int tid  = threadIdx.x;
    const int row0 = (int)crank * SLICE;

    for (int j = tid; j < MM; j += 256) S->v[j] = 1.0f;
    if (tid == 0) {
        mb_init(smem_u32(&S->mbu), 1);
        mb_init(smem_u32(&S->mbv), 1);
    }
    const int rnp = (g_rcnt[b * NN + row0 + tid] + 1) >> 1;   // uint4 pair slots
    const int cnp = (g_ccnt[b * MM + row0 + tid] + 1) >> 1;

    const uint4* prow = g_rell4 + (size_t)b * PAIRS * NN + (row0 + tid);
    const uint4* pcol = g_cell4 + (size_t)b * PAIRS * MM + (row0 + tid);

    // one-time preload, zero-padded to RSTAGE (zero entries are FMA no-ops)
    const int rs = (rnp < RSTAGE) ? rnp : RSTAGE;
    const int cs = (cnp < RSTAGE) ? cnp : RSTAGE;
    for (int k = 0; k < rs; k++) S->bufR[k * 256 + tid] = prow[(size_t)k * NN];
    for (int k = rs; k < RSTAGE; k++) S->bufR[k * 256 + tid] = make_uint4(0u, 0u, 0u, 0u);
    for (int k = 0; k < cs; k++) S->bufC[k * 256 + tid] = pcol[(size_t)k * MM];
    for (int k = cs; k < RSTAGE; k++) S->bufC[k * 256 + tid] = make_uint4(0u, 0u, 0u, 0u);

    const uint32_t mbu = smem_u32(&S->mbu), mbv = smem_u32(&S->mbv);
    const uint32_t usend = smem_u32(S->u) + (uint32_t)(row0 + (tid & ~3)) * 4u;
    const uint32_t vsend = smem_u32(S->v) + (uint32_t)(row0 + (tid & ~3)) * 4u;
    const bool sender = !(tid & 3);
    const uint4* bR = S->bufR + tid;
    const uint4* bC = S->bufC + tid;

    CLUSTER_SYNC();   // v init + peers' mbarriers live before any st.async lands

    for (int iter = 0; iter < NITER; iter++) {
        const uint32_t par = (uint32_t)(iter & 1);

        // ---- phase A: u from v ----
        if (tid == 0) mb_expect(mbu, TXB);
        {
            float a0 = 0.0f, a1 = 0.0f;
#pragma unroll
            for (int pk = 0; pk < RSTAGE; pk++) {   // fixed trip: loads front-batch
                uint4 e = bR[pk * 256];
                a0 = fmaf(uaf(e.y), S->v[e.x], a0);
                a1 = fmaf(uaf(e.w), S->v[e.z], a1);
            }
            for (int pk = RSTAGE; pk < rnp; pk++) {   // very rare heavy-row tail
                uint4 e = prow[(size_t)pk * NN];
                a0 = fmaf(uaf(e.y), S->v[e.x], a0);
                a1 = fmaf(uaf(e.w), S->v[e.z], a1);
            }
            // KFLOOR*S_v <= 2e-14 is absorbed by the 1e-8 clamp; drop it.
            float u = __fdividef(MUV, fmaxf(a0 + a1, EPSDIV));
            float u1 = __shfl_down_sync(0xffffffffu, u, 1);
            float u2 = __shfl_down_sync(0xffffffffu, u, 2);
            float u3 = __shfl_down_sync(0xffffffffu, u, 3);
            if (sender) {
#pragma unroll
                for (uint32_t r = 0; r < CL; r++)
                    st_async128(mapa_sh(usend, r),
                                __float_as_uint(u), __float_as_uint(u1),
                                __float_as_uint(u2), __float_as_uint(u3),
                                mapa_sh(mbu, r));
            }
        }
        mb_wait(mbu, par);   // acquire: all 2048 u values (incl. local) visible

        // ---- phase B: v from u ----
        if (tid == 0) mb_expect(mbv, TXB);
        {
            float a0 = 0.0f, a1 = 0.0f;
#pragma unroll
            for (int pk = 0; pk < RSTAGE; pk++) {
                uint4 e = bC[pk * 256];
                a0 = fmaf(uaf(e.y), S->u[e.x], a0);
                a1 = fmaf(uaf(e.w), S->u[e.z], a1);
            }
            for (int pk = RSTAGE; pk < cnp; pk++) {
                uint4 e = pcol[(size_t)pk * MM];
                a0 = fmaf(uaf(e.y), S->u[e.x], a0);
                a1 = fmaf(uaf(e.w), S->u[e.z], a1);
            }
            float v = __fdividef(MUV, fmaxf(a0 + a1, EPSDIV));
            float v1 = __shfl_down_sync(0xffffffffu, v, 1);
            float v2 = __shfl_down_sync(0xffffffffu, v, 2);
            float v3 = __shfl_down_sync(0xffffffffu, v, 3);
            if (sender) {
#pragma unroll
                for (uint32_t r = 0; r < CL; r++)
                    st_async128(mapa_sh(vsend, r),
                                __float_as_uint(v), __float_as_uint(v1),
                                __float_as_uint(v2), __float_as_uint(v3),
                                mapa_sh(mbv, r));
            }
        }
        mb_wait(mbv, par);
    }

    g_u[b * NN + row0 + tid] = S->u[row0 + tid];
    g_v[b * MM + row0 + tid] = S->v[row0 + tid];
    CLUSTER_SYNC();   // no CTA exits with peer traffic in flight
}

// ---------------------------------------------------------------------------
// emd_b = sum_i u_i * ( KFLOOR * sum_j d_ij v_j + sum_sparse (K~ d)_ij v_j )
__global__ void emd_kernel(const float* __restrict__ src, const float* __restrict__ tgt) {
    const int b = blockIdx.y;
    __shared__ float tx[MM], ty[MM], tz[MM], vv[MM];
    __shared__ float redw[8];
    const float* T = tgt + (size_t)b * MM * 3;
    for (int j = threadIdx.x; j < MM; j += blockDim.x) {
        tx[j] = T[3 * j + 0];
        ty[j] = T[3 * j + 1];
        tz[j] = T[3 * j + 2];
        vv[j] = g_v[b * MM + j];
    }
    __syncthreads();

    const int warp = threadIdx.x >> 5, lane = threadIdx.x & 31;
    const int nwarps = blockDim.x >> 5;
    const int rows_per_cta = NN / gridDim.x;
    const int row0 = blockIdx.x * rows_per_cta;
    const float* S = src + (size_t)b * NN * 3;
    const uint4* eell = g_eell4 + (size_t)b * PAIRS * NN;

    float wacc = 0.0f;
    for (int i = row0 + warp; i < row0 + rows_per_cta; i += nwarps) {
        const float sx = S[3 * i + 0], sy = S[3 * i + 1], sz = S[3 * i + 2];
        const float ui = g_u[b * NN + i];
        float dacc = 0.0f;
        for (int j0 = 0; j0 < MM; j0 += 32) {
            const int j = j0 + lane;
            float dx = sx - tx[j];
            float dy = sy - ty[j];
            float dz = sz - tz[j];
            float s = fmaf(dx, dx, fmaf(dy, dy, dz * dz));
            dacc = fmaf(sqrtf(s), vv[j], dacc);
        }
        float sacc = 0.0f;
        const int np = (g_rcnt[b * NN + i] + 1) >> 1;
        const uint4* p = eell + i;
        for (int pp = lane; pp < np; pp += 32) {
            uint4 e = p[(size_t)pp * NN];
            sacc = fmaf(uaf(e.y), vv[e.x], sacc);
            sacc = fmaf(uaf(e.w), vv[e.z], sacc);
        }
        float tot = fmaf(KFLOOR, dacc, sacc);
#pragma unroll
        for (int o = 16; o > 0; o >>= 1) tot += __shfl_xor_sync(0xffffffffu, tot, o);
        if (lane == 0) wacc = fmaf(ui, tot, wacc);
    }
    if (lane == 0) redw[warp] = wacc;
    __syncthreads();
    if (threadIdx.x == 0) {
        float s = 0.0f;
        for (int w = 0; w < nwarps; w++) s += redw[w];
        atomicAdd(&g_accum, s);
    }
}

__global__ void finalize_kernel(float* out) { out[0] = g_accum * (1.0f / BB); }

// ---------------------------------------------------------------------------
extern "C" void kernel_launch(void* const* d_in, const int* in_sizes, int n_in,
                              void* d_out, int out_size) {
    (void)in_sizes; (void)n_in; (void)out_size;
    const float* src = (const float*)d_in[0];
    const float* tgt = (const float*)d_in[1];
    float* out = (float*)d_out;

    cudaFuncSetAttribute(sinkhorn_kernel, cudaFuncAttributeMaxDynamicSharedMemorySize,
                         (int)sizeof(SKm));

    // 6 launches/call (same shape whose ncu capture hits sinkhorn).
    init_kernel<<<64, 256>>>();
    build_kernel<<<dim3(64, BB), 256>>>(src, tgt);
    colfix_kernel<<<64, 256>>>();
    sinkhorn_kernel<<<BB * CL, 256, sizeof(SKm)>>>();
    emd_kernel<<<dim3(64, BB), 256>>>(src, tgt);
    finalize_kernel<<<1, 1>>>(out);
}

// round 17
// speedup vs baseline: 1.4201x; 1.4201x over previous
#include <cuda_runtime.h>
#include <math.h>
#include <stdint.h>

#define BB 8
#define NN 2048
#define MM 2048
#define STRIDE 512            /* max sparse entries per row/col in gmem ELL */
#define PAIRS (STRIDE / 2)
#define NITER 100
#define CL 8                  /* CTAs per cluster (= per batch) */
#define SLICE 256             /* rows/cols owned per CTA        */
#define RSTAGE 22             /* pair slots per thread resident in SMEM     */
#define TXB1 1024u            /* per-phase incoming bytes PER SOURCE RANK: 256 x 4B */

#define KFLOOR 1.9287498479639178e-22f   /* fp32(exp(-50)) */
#define MUV    4.8828125e-4f             /* 1/2048 */
#define EPSDIV 1e-8f

static __device__ __forceinline__ float uaf(unsigned x) { return __uint_as_float(x); }

// ---- static device scratch (no runtime allocations allowed) ----
__device__ uint4 g_rell4[(size_t)BB * PAIRS * NN];   // (j, Ktilde)    row-major ELL
__device__ uint4 g_cell4[(size_t)BB * PAIRS * MM];   // (i, Ktilde)    col-major ELL
__device__ uint4 g_eell4[(size_t)BB * PAIRS * NN];   // (j, Ktilde*d)  row-major ELL (emd)
__device__ int   g_rcnt[BB * NN];
__device__ int   g_ccnt[BB * MM];
__device__ float g_u[BB * NN];
__device__ float g_v[BB * MM];
__device__ float g_accum;

// ---- dynamic SMEM (~197 KB) ----
struct SKm {
    float u[NN];
    float v[MM];
    uint4 bufR[RSTAGE * 256];   // resident row entries, layout [k][tid]
    uint4 bufC[RSTAGE * 256];   // resident col entries
    unsigned long long mbu[CL], mbv[CL];   // one mbarrier per SOURCE rank
};

// ---- cluster / DSMEM / mbarrier helpers ----
static __device__ __forceinline__ uint32_t smem_u32(const void* p) {
    return (uint32_t)__cvta_generic_to_shared(p);
}
static __device__ __forceinline__ uint32_t mapa_sh(uint32_t addr, uint32_t rank) {
    uint32_t o;
    asm("mapa.shared::cluster.u32 %0, %1, %2;" : "=r"(o) : "r"(addr), "r"(rank));
    return o;
}
static __device__ __forceinline__ void st_async64(uint32_t daddr, unsigned long long v, uint32_t dmbar) {
    asm volatile("st.async.shared::cluster.mbarrier::complete_tx::bytes.u64 [%0], %1, [%2];"
                 :: "r"(daddr), "l"(v), "r"(dmbar) : "memory");
}
static __device__ __forceinline__ void mb_init(uint32_t mb, uint32_t cnt) {
    asm volatile("mbarrier.init.shared.b64 [%0], %1;" :: "r"(mb), "r"(cnt) : "memory");
}
static __device__ __forceinline__ void mb_expect(uint32_t mb, uint32_t tx) {
    asm volatile("mbarrier.arrive.expect_tx.shared.b64 _, [%0], %1;" :: "r"(mb), "r"(tx) : "memory");
}
static __device__ __forceinline__ void mb_wait(uint32_t mb, uint32_t parity) {
    uint32_t done;
    asm volatile("{\n\t.reg .pred p;\n\t"
                 "mbarrier.try_wait.parity.acquire.cluster.shared::cta.b64 p, [%1], %2;\n\t"
                 "selp.b32 %0, 1, 0, p;\n\t}"
                 : "=r"(done) : "r"(mb), "r"(parity) : "memory");
    while (!done) {
        asm volatile("{\n\t.reg .pred p;\n\t"
                     "mbarrier.try_wait.parity.acquire.cluster.shared::cta.b64 p, [%1], %2, 0x989680;\n\t"
                     "selp.b32 %0, 1, 0, p;\n\t}"
                     : "=r"(done) : "r"(mb), "r"(parity) : "memory");
    }
}
#define CLUSTER_SYNC() do {                                                 \
    asm volatile("barrier.cluster.arrive.aligned;" ::: "memory");           \
    asm volatile("barrier.cluster.wait.aligned;"   ::: "memory");           \
} while (0)

// ---------------------------------------------------------------------------
__global__ void init_kernel() {
    int t = blockIdx.x * blockDim.x + threadIdx.x;
    if (t < BB * MM) g_ccnt[t] = 0;
    if (t == 0) g_accum = 0.0f;
}

// ---------------------------------------------------------------------------
// Build sparse correction lists where d^2 < 0.25 (100*d < 50); elsewhere
// K == exp(-50) exactly (same bits as the reference clamp).
__global__ void build_kernel(const float* __restrict__ src, const float* __restrict__ tgt) {
    const int b = blockIdx.y;
    __shared__ float tx[MM], ty[MM], tz[MM];
    const float* T = tgt + (size_t)b * MM * 3;
    for (int j = threadIdx.x; j < MM; j += blockDim.x) {
        tx[j] = T[3 * j + 0];
        ty[j] = T[3 * j + 1];
        tz[j] = T[3 * j + 2];
    }
    __syncthreads();

    const int warp = threadIdx.x >> 5, lane = threadIdx.x & 31;
    const int nwarps = blockDim.x >> 5;
    const int rows_per_cta = NN / gridDim.x;
    const int row0 = blockIdx.x * rows_per_cta;
    const float* S = src + (size_t)b * NN * 3;
    uint2* rell2 = (uint2*)(g_rell4 + (size_t)b * PAIRS * NN);
    uint2* eell2 = (uint2*)(g_eell4 + (size_t)b * PAIRS * NN);
    uint2* cell2 = (uint2*)(g_cell4 + (size_t)b * PAIRS * MM);

    for (int i = row0 + warp; i < row0 + rows_per_cta; i += nwarps) {
        const float sx = S[3 * i + 0], sy = S[3 * i + 1], sz = S[3 * i + 2];
        int rbase = 0;
        for (int j0 = 0; j0 < MM; j0 += 32) {
            const int j = j0 + lane;
            float dx = sx - tx[j];
            float dy = sy - ty[j];
            float dz = sz - tz[j];
            float s = fmaf(dx, dx, fmaf(dy, dy, dz * dz));
            bool pred = (s < 0.25f);
            unsigned mask = __ballot_sync(0xffffffffu, pred);
            if (pred) {
                float d = sqrtf(s);
                float kt = expf(-100.0f * d) - KFLOOR;
                int k = rbase + __popc(mask & ((1u << lane) - 1u));
                if (k < STRIDE) {
                    size_t i2 = ((size_t)(k >> 1) * NN + i) * 2 + (k & 1);
                    rell2[i2] = make_uint2((unsigned)j, __float_as_uint(kt));
                    eell2[i2] = make_uint2((unsigned)j, __float_as_uint(kt * d));
                }
                int kc = atomicAdd(&g_ccnt[b * MM + j], 1);
                if (kc < STRIDE)
                    cell2[((size_t)(kc >> 1) * MM + j) * 2 + (kc & 1)] =
                        make_uint2((unsigned)i, __float_as_uint(kt));
            }
            rbase += __popc(mask);
        }
        int cap = (rbase < STRIDE) ? rbase : STRIDE;
        if (lane == 0) {
            g_rcnt[b * NN + i] = cap;
            if (cap & 1) {   // zero-pad ELL odd tail (cap==STRIDE is even)
                size_t i2 = ((size_t)(cap >> 1) * NN + i) * 2 + 1;
                rell2[i2] = make_uint2(0u, 0u);
                eell2[i2] = make_uint2(0u, 0u);
            }
        }
    }
}

// Clamp column counts + zero-pad odd tails of the column lists.
__global__ void colfix_kernel() {
    int t = blockIdx.x * blockDim.x + threadIdx.x;
    if (t >= BB * MM) return;
    int c = g_ccnt[t];
    if (c > STRIDE) c = STRIDE;
    g_ccnt[t] = c;
    if (c & 1) {
        int b = t / MM, j = t - b * MM;
        uint2* cell2 = (uint2*)(g_cell4 + (size_t)b * PAIRS * MM);
        cell2[((size_t)(c >> 1) * MM + j) * 2 + 1] = make_uint2(0u, 0u);
    }
}

// ---------------------------------------------------------------------------
// 256 threads/CTA, one thread per owned row+col. ELL lists resident in SMEM
// (loaded once; dynamic-trip gather as in R13). Broadcast: st.async pairs to
// all 8 ranks, but each SOURCE rank targets its OWN destination mbarrier
// (8 per direction) -> tx-update serialization parallelized 8x. Only threads
// 0..7 wait (one per source barrier, concurrently); everyone else parks at a
// __syncthreads -> no 256-thread spin hammering the SMEM port during delivery.
__global__ void __launch_bounds__(256, 1) __cluster_dims__(CL, 1, 1)
sinkhorn_kernel() {
    extern __shared__ char raw[];
    SKm* S = (SKm*)raw;
    uint32_t crank;
    asm("mov.u32 %0, %%cluster_ctarank;" : "=r"(crank));
    const int b    = blockIdx.x >> 3;
    const int tid  = threadIdx.x;
    const int row0 = (int)crank * SLICE;

    for (int j = tid; j < MM; j += 256) S->v[j] = 1.0f;
    const uint32_t mbu0 = smem_u32(S->mbu);   // base of 8 source-rank barriers
    const uint32_t mbv0 = smem_u32(S->mbv);
    if (tid < CL) {
        mb_init(mbu0 + (uint32_t)tid * 8u, 1);
        mb_init(mbv0 + (uint32_t)tid * 8u, 1);
    }
    const int rnp = (g_rcnt[b * NN + row0 + tid] + 1) >> 1;   // uint4 pair slots
    const int cnp = (g_ccnt[b * MM + row0 + tid] + 1) >> 1;

    const uint4* prow = g_rell4 + (size_t)b * PAIRS * NN + (row0 + tid);
    const uint4* pcol = g_cell4 + (size_t)b * PAIRS * MM + (row0 + tid);

    // one-time preload of entry lists into SMEM (coalesced across tid)
    const int rs = (rnp < RSTAGE) ? rnp : RSTAGE;
    const int cs = (cnp < RSTAGE) ? cnp : RSTAGE;
    for (int k = 0; k < rs; k++) S->bufR[k * 256 + tid] = prow[(size_t)k * NN];
    for (int k = 0; k < cs; k++) S->bufC[k * 256 + tid] = pcol[(size_t)k * MM];

    const uint32_t usend = smem_u32(S->u) + (uint32_t)(row0 + (tid & ~1)) * 4u;
    const uint32_t vsend = smem_u32(S->v) + (uint32_t)(row0 + (tid & ~1)) * 4u;
    const uint32_t my_mbu = mbu0 + crank * 8u;   // my slot in each destination
    const uint32_t my_mbv = mbv0 + crank * 8u;
    const bool sender = !(tid & 1);
    const uint4* bR = S->bufR + tid;
    const uint4* bC = S->bufC + tid;

    CLUSTER_SYNC();   // v init + peers' mbarriers live before any st.async lands

    for (int iter = 0; iter < NITER; iter++) {
        const uint32_t par = (uint32_t)(iter & 1);

        // ---- phase A: u from v ----
        if (tid < CL) mb_expect(mbu0 + (uint32_t)tid * 8u, TXB1);
        {
            float a0 = 0.0f, a1 = 0.0f;
#pragma unroll 4
            for (int pk = 0; pk < rs; pk++) {
                uint4 e = bR[pk * 256];
                a0 = fmaf(uaf(e.y), S->v[e.x], a0);
                a1 = fmaf(uaf(e.w), S->v[e.z], a1);
            }
            for (int pk = RSTAGE; pk < rnp; pk++) {   // very rare heavy-row tail
                uint4 e = prow[(size_t)pk * NN];
                a0 = fmaf(uaf(e.y), S->v[e.x], a0);
                a1 = fmaf(uaf(e.w), S->v[e.z], a1);
            }
            // KFLOOR*S_v <= 2e-14 is absorbed by the 1e-8 clamp; drop it.
            float u = __fdividef(MUV, fmaxf(a0 + a1, EPSDIV));
            float u1 = __shfl_down_sync(0xffffffffu, u, 1);
            if (sender) {
                unsigned long long pk2 =
                    ((unsigned long long)__float_as_uint(u1) << 32) | __float_as_uint(u);
#pragma unroll
                for (uint32_t r = 0; r < CL; r++)
                    st_async64(mapa_sh(usend, r), pk2, mapa_sh(my_mbu, r));
            }
        }
        if (tid < CL) mb_wait(mbu0 + (uint32_t)tid * 8u, par);   // 8 parallel waits
        __syncthreads();   // publishes all landed u values CTA-wide

        // ---- phase B: v from u ----
        if (tid < CL) mb_expect(mbv0 + (uint32_t)tid * 8u, TXB1);
        {
            float a0 = 0.0f, a1 = 0.0f;
#pragma unroll 4
            for (int pk = 0; pk < cs; pk++) {
                uint4 e = bC[pk * 256];
                a0 = fmaf(uaf(e.y), S->u[e.x], a0);
                a1 = fmaf(uaf(e.w), S->u[e.z], a1);
            }
            for (int pk = RSTAGE; pk < cnp; pk++) {
                uint4 e = pcol[(size_t)pk * MM];
                a0 = fmaf(uaf(e.y), S->u[e.x], a0);
                a1 = fmaf(uaf(e.w), S->u[e.z], a1);
            }
            float v = __fdividef(MUV, fmaxf(a0 + a1, EPSDIV));
            float v1 = __shfl_down_sync(0xffffffffu, v, 1);
            if (sender) {
                unsigned long long pk2 =
                    ((unsigned long long)__float_as_uint(v1) << 32) | __float_as_uint(v);
#pragma unroll
                for (uint32_t r = 0; r < CL; r++)
                    st_async64(mapa_sh(vsend, r), pk2, mapa_sh(my_mbv, r));
            }
        }
        if (tid < CL) mb_wait(mbv0 + (uint32_t)tid * 8u, par);
        __syncthreads();
    }

    g_u[b * NN + row0 + tid] = S->u[row0 + tid];
    g_v[b * MM + row0 + tid] = S->v[row0 + tid];
    CLUSTER_SYNC();   // no CTA exits with peer traffic in flight
}

// ---------------------------------------------------------------------------
// emd_b = sum_i u_i * ( KFLOOR * sum_j d_ij v_j + sum_sparse (K~ d)_ij v_j )
__global__ void emd_kernel(const float* __restrict__ src, const float* __restrict__ tgt) {
    const int b = blockIdx.y;
    __shared__ float tx[MM], ty[MM], tz[MM], vv[MM];
    __shared__ float redw[8];
    const float* T = tgt + (size_t)b * MM * 3;
    for (int j = threadIdx.x; j < MM; j += blockDim.x) {
        tx[j] = T[3 * j + 0];
        ty[j] = T[3 * j + 1];
        tz[j] = T[3 * j + 2];
        vv[j] = g_v[b * MM + j];
    }
    __syncthreads();

    const int warp = threadIdx.x >> 5, lane = threadIdx.x & 31;
    const int nwarps = blockDim.x >> 5;
    const int rows_per_cta = NN / gridDim.x;
    const int row0 = blockIdx.x * rows_per_cta;
    const float* S = src + (size_t)b * NN * 3;
    const uint4* eell = g_eell4 + (size_t)b * PAIRS * NN;

    float wacc = 0.0f;
    for (int i = row0 + warp; i < row0 + rows_per_cta; i += nwarps) {
        const float sx = S[3 * i + 0], sy = S[3 * i + 1], sz = S[3 * i + 2];
        const float ui = g_u[b * NN + i];
        float dacc = 0.0f;
        for (int j0 = 0; j0 < MM; j0 += 32) {
            const int j = j0 + lane;
            float dx = sx - tx[j];
            float dy = sy - ty[j];
            float dz = sz - tz[j];
            float s = fmaf(dx, dx, fmaf(dy, dy, dz * dz));
            dacc = fmaf(sqrtf(s), vv[j], dacc);
        }
        float sacc = 0.0f;
        const int np = (g_rcnt[b * NN + i] + 1) >> 1;
        const uint4* p = eell + i;
        for (int pp = lane; pp < np; pp += 32) {
            uint4 e = p[(size_t)pp * NN];
            sacc = fmaf(uaf(e.y), vv[e.x], sacc);
            sacc = fmaf(uaf(e.w), vv[e.z], sacc);
        }
        float tot = fmaf(KFLOOR, dacc, sacc);
#pragma unroll
        for (int o = 16; o > 0; o >>= 1) tot += __shfl_xor_sync(0xffffffffu, tot, o);
        if (lane == 0) wacc = fmaf(ui, tot, wacc);
    }
    if (lane == 0) redw[warp] = wacc;
    __syncthreads();
    if (threadIdx.x == 0) {
        float s = 0.0f;
        for (int w = 0; w < nwarps; w++) s += redw[w];
        atomicAdd(&g_accum, s);
    }
}

__global__ void finalize_kernel(float* out) { out[0] = g_accum * (1.0f / BB); }

// ---------------------------------------------------------------------------
extern "C" void kernel_launch(void* const* d_in, const int* in_sizes, int n_in,
                              void* d_out, int out_size) {
    (void)in_sizes; (void)n_in; (void)out_size;
    const float* src = (const float*)d_in[0];
    const float* tgt = (const float*)d_in[1];
    float* out = (float*)d_out;

    cudaFuncSetAttribute(sinkhorn_kernel, cudaFuncAttributeMaxDynamicSharedMemorySize,
                         (int)sizeof(SKm));

    // 6 launches/call (same shape whose ncu capture hits sinkhorn).
    init_kernel<<<64, 256>>>();
    build_kernel<<<dim3(64, BB), 256>>>(src, tgt);
    colfix_kernel<<<64, 256>>>();
    sinkhorn_kernel<<<BB * CL, 256, sizeof(SKm)>>>();
    emd_kernel<<<dim3(64, BB), 256>>>(src, tgt);
    finalize_kernel<<<1, 1>>>(out);
}